// round 17
// baseline (speedup 1.0000x reference)
#include <cuda_runtime.h>
#include <cstdint>

// Per-token int4 quantization (single-pass, block-per-row) — R8 config +
// REDUX warp reduction:
//   x: [N, H] fp32 (H = 4096)
//   scales[n] = max|x[n,:]| / 7
//   q = rint(x * 7/max)   (in [-7,7] by construction; clamp-free)
//   packed byte = ((q_odd & 0xF) << 4) | (q_even & 0xF)  (signed int8 value)
//
// Warp max uses __reduce_max_sync on the |x| bit pattern (monotonic for
// non-negative floats): one REDUX.MAX (~30cyc) replaces a 5-step SHFL+FMAX
// chain (~150cyc) on the pre-barrier critical path.
//
// Measured-best config (R8/R16): float4 __ldcs loads, lane-consecutive
// float2 write-back stores (replay-overwrite L2 residency), 256 thr/CTA,
// one CTA per row.
//
// Harness output layout (detected via out_size):
//   FLOAT_OUT: [N*H/2 float32 (packed byte values)][N float32 scales]
//   BYTE_OUT : [N*H/2 int8][N float32 scales]

constexpr int H       = 4096;
constexpr int THREADS = 256;
constexpr int CHUNKS  = H / 4 / THREADS;  // 4 float4-chunks per thread

template <bool FLOAT_OUT>
__global__ __launch_bounds__(THREADS, 8)
void quant_int4_kernel(const float* __restrict__ x,
                       void* __restrict__ packed_out,
                       float* __restrict__ scales)
{
    const int row = blockIdx.x;
    const int t   = threadIdx.x;

    const float4* xr = reinterpret_cast<const float4*>(x + (size_t)row * H);

    // Coalesced streaming loads: lane-consecutive float4 per LDG.128,
    // all 4 front-batched for max MLP.
    float4 v[CHUNKS];
#pragma unroll
    for (int k = 0; k < CHUNKS; ++k)
        v[k] = __ldcs(&xr[t + THREADS * k]);

    // Local max|x|
    float m = 0.0f;
#pragma unroll
    for (int k = 0; k < CHUNKS; ++k) {
        m = fmaxf(m, fmaxf(fmaxf(fabsf(v[k].x), fabsf(v[k].y)),
                           fmaxf(fabsf(v[k].z), fabsf(v[k].w))));
    }

    // Warp reduce in one REDUX.MAX: |x| >= 0 so the fp32 bit pattern is
    // monotonic under unsigned compare.
    uint32_t mbits = __reduce_max_sync(0xffffffffu, __float_as_uint(m));

    __shared__ uint32_t smax[THREADS / 32];
    if ((t & 31) == 0) smax[t >> 5] = mbits;
    __syncthreads();

    uint32_t rbits = smax[0];
#pragma unroll
    for (int w = 1; w < THREADS / 32; ++w)
        rbits = max(rbits, smax[w]);
    const float rowmax = __uint_as_float(rbits);

    const float scale = rowmax / 7.0f;                        // exact fp32
    const float inv   = (rowmax > 0.0f) ? 7.0f / rowmax : 0.0f;

    if (t == 0) scales[row] = scale;

    // Quantize each float4 chunk -> 2 packed byte values. Clamp-free:
    // |x| <= rowmax implies |x*inv| <= 7 (+1ulp), rint stays in [-7,7].
    if (FLOAT_OUT) {
        float2* op = reinterpret_cast<float2*>((float*)packed_out + (size_t)row * (H / 2));
#pragma unroll
        for (int k = 0; k < CHUNKS; ++k) {
            // rintf == FRND round-half-even, matches reference rounding.
            float q0 = rintf(v[k].x * inv);
            float q1 = rintf(v[k].y * inv);
            float q2 = rintf(v[k].z * inv);
            float q3 = rintf(v[k].w * inv);
            // low-nibble value: q + 16 if q < 0 (maps [-8,-1] -> [8,15])
            float n0 = q0 + (q0 < 0.0f ? 16.0f : 0.0f);
            float n2 = q2 + (q2 < 0.0f ? 16.0f : 0.0f);
            float b0 = fmaf(16.0f, q1, n0);   // exact: small integers
            float b1 = fmaf(16.0f, q3, n2);
            op[t + THREADS * k] = make_float2(b0, b1);   // default write-back
        }
    } else {
        uint16_t* op = reinterpret_cast<uint16_t*>((int8_t*)packed_out + (size_t)row * (H / 2));
#pragma unroll
        for (int k = 0; k < CHUNKS; ++k) {
            int q0 = __float2int_rn(v[k].x * inv);
            int q1 = __float2int_rn(v[k].y * inv);
            int q2 = __float2int_rn(v[k].z * inv);
            int q3 = __float2int_rn(v[k].w * inv);
            uint16_t b = (uint16_t)((((q3 & 0xF) << 4) | (q2 & 0xF)) << 8
                                  | (((q1 & 0xF) << 4) | (q0 & 0xF)));
            op[t + THREADS * k] = b;
        }
    }
}

extern "C" void kernel_launch(void* const* d_in, const int* in_sizes, int n_in,
                              void* d_out, int out_size)
{
    const float* x = (const float*)d_in[0];
    const int rows = in_sizes[0] / H;
    const long long packed_elems = (long long)rows * (H / 2);

    if ((long long)out_size == packed_elems + rows) {
        // float32 layout: packed values as floats, then scales
        float* packed = (float*)d_out;
        float* scales = packed + packed_elems;
        quant_int4_kernel<true><<<rows, THREADS>>>(x, packed, scales);
    } else {
        // int8 layout: packed bytes, then fp32 scales appended as raw bytes
        int8_t* packed = (int8_t*)d_out;
        float*  scales = (float*)(packed + packed_elems);
        quant_int4_kernel<false><<<rows, THREADS>>>(x, packed, scales);
    }
}